// round 2
// baseline (speedup 1.0000x reference)
#include <cuda_runtime.h>

// GHMRankingLoss: result = (1/N) * sum_b max(count_b,1)^-0.75 * sum_{i in bin b} loss_i
//
// Two launches (graph-capturable, allocation-free):
//   1) ghm_main_k:  one pass over the 3 input arrays. Per-lane private smem
//      histograms (no atomics, conflict-free), MUFU-free threshold binning,
//      unroll-2 grid-stride with front-batched float4 loads. Each block
//      writes its 10 per-bin (loss_sum, count) partials to its own slot in a
//      __device__ array -> no global zero-init kernel needed.
//   2) ghm_final_k: 10 warps reduce the 1024x10 partials in double and apply
//      w_b = max(c_b,1)^-0.75, writing the scalar mean.

#define BINS 10
#define NT 256
#define NB 1024   // 1024*256 threads = 2^18: divides N/4 = 2^22 evenly

__device__ float2 g_part[NB * BINS];   // per-block per-bin (loss_sum, count)

// bin = clip(floor(10*sigmoid(x)), 0, 9) via exact logit thresholds:
//   sigmoid(x) >= k/10  <=>  x >= ln(k/(10-k));  thresholds are symmetric.
__device__ __forceinline__ int ghm_bin(float x) {
    float ax = fabsf(x);
    int m = 0;
    m += (ax >= 0.40546511f);   // ln(6/4)
    m += (ax >= 0.84729786f);   // ln(7/3)
    m += (ax >= 1.38629436f);   // ln(8/2)
    m += (ax >= 2.19722458f);   // ln(9/1)
    return (x >= 0.0f) ? (5 + m) : (4 - m);
}

__device__ __forceinline__ void ghm_accum(float2* __restrict__ h,
                                          float o1, float o2, float t) {
    float diff = o1 - o2;
    float loss = fmaxf(0.0f, -t * diff);      // margin = 0
    float es   = fmaf(2.0f, t, -1.0f);        // expected_sign = 2t-1
    float x    = -diff * es;                  // sigmoid argument
    int bi = ghm_bin(x);
    // per-lane private slot: stride NT floats2 between bins -> no conflicts
    float2 v = h[bi * NT];
    v.x += loss;
    v.y += 1.0f;
    h[bi * NT] = v;
}

__global__ void __launch_bounds__(NT)
ghm_main_k(const float* __restrict__ o1,
           const float* __restrict__ o2,
           const float* __restrict__ tg,
           int n) {
    __shared__ float2 hist[BINS * NT];
    const int tid = threadIdx.x;

    #pragma unroll
    for (int b = 0; b < BINS; b++)
        hist[b * NT + tid] = make_float2(0.0f, 0.0f);
    __syncthreads();

    float2* h = &hist[tid];

    const int n4     = n >> 2;
    const int stride = NB * NT;
    int i = blockIdx.x * NT + tid;

    const float4* __restrict__ A = (const float4*)o1;
    const float4* __restrict__ B = (const float4*)o2;
    const float4* __restrict__ T = (const float4*)tg;

    // unroll-2: 6 front-batched LDG.128 per iteration for MLP
    for (; i + stride < n4; i += 2 * stride) {
        float4 a0 = __ldcs(A + i);
        float4 b0 = __ldcs(B + i);
        float4 t0 = __ldcs(T + i);
        float4 a1 = __ldcs(A + i + stride);
        float4 b1 = __ldcs(B + i + stride);
        float4 t1 = __ldcs(T + i + stride);
        ghm_accum(h, a0.x, b0.x, t0.x);
        ghm_accum(h, a0.y, b0.y, t0.y);
        ghm_accum(h, a0.z, b0.z, t0.z);
        ghm_accum(h, a0.w, b0.w, t0.w);
        ghm_accum(h, a1.x, b1.x, t1.x);
        ghm_accum(h, a1.y, b1.y, t1.y);
        ghm_accum(h, a1.z, b1.z, t1.z);
        ghm_accum(h, a1.w, b1.w, t1.w);
    }
    for (; i < n4; i += stride) {
        float4 a = __ldcs(A + i);
        float4 b = __ldcs(B + i);
        float4 t = __ldcs(T + i);
        ghm_accum(h, a.x, b.x, t.x);
        ghm_accum(h, a.y, b.y, t.y);
        ghm_accum(h, a.z, b.z, t.z);
        ghm_accum(h, a.w, b.w, t.w);
    }
    // scalar tail (n not multiple of 4)
    for (int j = (n4 << 2) + blockIdx.x * NT + tid; j < n; j += stride)
        ghm_accum(h, o1[j], o2[j], tg[j]);

    __syncthreads();

    // tree-reduce the 256 lanes for all 10 bins
    #pragma unroll
    for (int s = NT / 2; s >= 1; s >>= 1) {
        if (tid < s) {
            #pragma unroll
            for (int b = 0; b < BINS; b++) {
                float2 lo = hist[b * NT + tid];
                float2 hi = hist[b * NT + tid + s];
                lo.x += hi.x;
                lo.y += hi.y;
                hist[b * NT + tid] = lo;
            }
        }
        __syncthreads();
    }

    // every block writes its own 10 slots unconditionally -> no init kernel
    if (tid < BINS)
        g_part[blockIdx.x * BINS + tid] = hist[tid * NT];
}

__global__ void __launch_bounds__(320)
ghm_final_k(float* __restrict__ out, double inv_n) {
    const int w    = threadIdx.x >> 5;   // warp = bin (0..9)
    const int lane = threadIdx.x & 31;

    double s = 0.0, c = 0.0;
    for (int b = lane; b < NB; b += 32) {
        float2 p = g_part[b * BINS + w];
        s += (double)p.x;
        c += (double)p.y;
    }
    #pragma unroll
    for (int off = 16; off; off >>= 1) {
        s += __shfl_down_sync(0xffffffff, s, off);
        c += __shfl_down_sync(0xffffffff, c, off);
    }

    __shared__ double ss[BINS], cc[BINS];
    if (lane == 0) { ss[w] = s; cc[w] = c; }
    __syncthreads();

    if (threadIdx.x == 0) {
        double acc = 0.0;
        #pragma unroll
        for (int b = 0; b < BINS; b++) {
            double tot = cc[b] < 1.0 ? 1.0 : cc[b];   // clamp(min=1)
            acc += pow(tot, -0.75) * ss[b];           // w = tot^-alpha
        }
        out[0] = (float)(acc * inv_n);
    }
}

extern "C" void kernel_launch(void* const* d_in, const int* in_sizes, int n_in,
                              void* d_out, int out_size) {
    const float* o1 = (const float*)d_in[0];
    const float* o2 = (const float*)d_in[1];
    const float* tg = (const float*)d_in[2];
    float* out = (float*)d_out;
    int n = in_sizes[0];

    ghm_main_k<<<NB, NT>>>(o1, o2, tg, n);
    ghm_final_k<<<1, 320>>>(out, 1.0 / (double)n);
}

// round 3
// speedup vs baseline: 1.0344x; 1.0344x over previous
#include <cuda_runtime.h>

// GHMRankingLoss, fully fused single kernel:
//   result = (1/N) * sum_b max(count_b,1)^-0.75 * sum_{i in bin b} loss_i
//
// - One pass over the 3 fp32 arrays (201 MB), grid-stride, unroll-2 float4.
// - Per-lane private smem histograms (no atomics, conflict-free LDS.64).
// - MUFU-free binning: floor(10*sigmoid(x)) via 4 symmetric logit thresholds.
// - Block partials written bin-major to a __device__ array; the LAST block
//   (threadfence + ticket) reduces 592 partials/bin from L2 in double,
//   applies w_b = max(c,1)^-0.75, writes the scalar mean, resets the ticket.

#define BINS 10
#define NT 256
#define NB 592   // 4 CTAs/SM * 148 SMs -> one full wave, 32 warps/SM

__device__ float2 g_part[BINS * NB];       // bin-major: [bin][block]
__device__ unsigned int g_ticket;          // zero at load; last block resets

// bin = clip(floor(10*sigmoid(x)), 0, 9):  sigmoid(x) >= k/10 <=> x >= ln(k/(10-k))
__device__ __forceinline__ int ghm_bin(float x) {
    float ax = fabsf(x);
    int m = 0;
    m += (ax >= 0.40546511f);   // ln(6/4)
    m += (ax >= 0.84729786f);   // ln(7/3)
    m += (ax >= 1.38629436f);   // ln(8/2)
    m += (ax >= 2.19722458f);   // ln(9/1)
    return (x >= 0.0f) ? (5 + m) : (4 - m);
}

__device__ __forceinline__ void ghm_accum(float2* __restrict__ h,
                                          float o1, float o2, float t) {
    float diff = o1 - o2;
    float loss = fmaxf(0.0f, -t * diff);      // margin = 0
    float es   = fmaf(2.0f, t, -1.0f);        // expected_sign = 2t-1 (t=+-1 -> {1,-3})
    float x    = -diff * es;
    int bi = ghm_bin(x);
    float2 v = h[bi * NT];                    // per-lane private slot
    v.x += loss;
    v.y += 1.0f;
    h[bi * NT] = v;
}

__global__ void __launch_bounds__(NT)
ghm_fused_k(const float* __restrict__ o1,
            const float* __restrict__ o2,
            const float* __restrict__ tg,
            float* __restrict__ out,
            int n) {
    __shared__ float2 hist[BINS * NT];
    const int tid = threadIdx.x;
    const int bid = blockIdx.x;

    #pragma unroll
    for (int b = 0; b < BINS; b++)
        hist[b * NT + tid] = make_float2(0.0f, 0.0f);
    __syncthreads();

    float2* h = &hist[tid];

    const int n4     = n >> 2;
    const int stride = NB * NT;
    int i = bid * NT + tid;

    const float4* __restrict__ A = (const float4*)o1;
    const float4* __restrict__ B = (const float4*)o2;
    const float4* __restrict__ T = (const float4*)tg;

    // unroll-2: 6 front-batched LDG.128 per iteration
    for (; i + stride < n4; i += 2 * stride) {
        float4 a0 = __ldcs(A + i);
        float4 b0 = __ldcs(B + i);
        float4 t0 = __ldcs(T + i);
        float4 a1 = __ldcs(A + i + stride);
        float4 b1 = __ldcs(B + i + stride);
        float4 t1 = __ldcs(T + i + stride);
        ghm_accum(h, a0.x, b0.x, t0.x);
        ghm_accum(h, a0.y, b0.y, t0.y);
        ghm_accum(h, a0.z, b0.z, t0.z);
        ghm_accum(h, a0.w, b0.w, t0.w);
        ghm_accum(h, a1.x, b1.x, t1.x);
        ghm_accum(h, a1.y, b1.y, t1.y);
        ghm_accum(h, a1.z, b1.z, t1.z);
        ghm_accum(h, a1.w, b1.w, t1.w);
    }
    for (; i < n4; i += stride) {
        float4 a = __ldcs(A + i);
        float4 b = __ldcs(B + i);
        float4 t = __ldcs(T + i);
        ghm_accum(h, a.x, b.x, t.x);
        ghm_accum(h, a.y, b.y, t.y);
        ghm_accum(h, a.z, b.z, t.z);
        ghm_accum(h, a.w, b.w, t.w);
    }
    for (int j = (n4 << 2) + bid * NT + tid; j < n; j += stride)
        ghm_accum(h, o1[j], o2[j], tg[j]);

    __syncthreads();

    // tree-reduce 256 lanes for all 10 bins
    #pragma unroll
    for (int s = NT / 2; s >= 1; s >>= 1) {
        if (tid < s) {
            #pragma unroll
            for (int b = 0; b < BINS; b++) {
                float2 lo = hist[b * NT + tid];
                float2 hi = hist[b * NT + tid + s];
                lo.x += hi.x;
                lo.y += hi.y;
                hist[b * NT + tid] = lo;
            }
        }
        __syncthreads();
    }

    // publish this block's 10 partials (bin-major), then grab a ticket
    if (tid < BINS)
        g_part[tid * NB + bid] = hist[tid * NT];

    __shared__ bool isLast;
    __threadfence();
    if (tid == 0) {
        unsigned int v = atomicAdd(&g_ticket, 1u);
        isLast = (v == NB - 1);
    }
    __syncthreads();
    if (!isLast) return;

    // ---- last block: reduce 592 partials per bin (L2-resident), finalize ----
    const int warp = tid >> 5;
    const int lane = tid & 31;
    __shared__ double ss[BINS], cc[BINS];

    for (int b = warp; b < BINS; b += NT / 32) {
        double s = 0.0, c = 0.0;
        for (int k = lane; k < NB; k += 32) {
            float2 p = g_part[b * NB + k];
            s += (double)p.x;
            c += (double)p.y;
        }
        #pragma unroll
        for (int off = 16; off; off >>= 1) {
            s += __shfl_down_sync(0xffffffff, s, off);
            c += __shfl_down_sync(0xffffffff, c, off);
        }
        if (lane == 0) { ss[b] = s; cc[b] = c; }
    }
    __syncthreads();

    if (tid == 0) {
        double acc = 0.0;
        #pragma unroll
        for (int b = 0; b < BINS; b++) {
            double tot = cc[b] < 1.0 ? 1.0 : cc[b];   // clamp(min=1)
            acc += pow(tot, -0.75) * ss[b];           // w = tot^-alpha
        }
        out[0] = (float)(acc / (double)n);
        g_ticket = 0;                                  // reset for graph replay
    }
}

extern "C" void kernel_launch(void* const* d_in, const int* in_sizes, int n_in,
                              void* d_out, int out_size) {
    const float* o1 = (const float*)d_in[0];
    const float* o2 = (const float*)d_in[1];
    const float* tg = (const float*)d_in[2];
    float* out = (float*)d_out;
    int n = in_sizes[0];

    ghm_fused_k<<<NB, NT>>>(o1, o2, tg, out, n);
}